// round 2
// baseline (speedup 1.0000x reference)
#include <cuda_runtime.h>

#define BB    4096
#define TT    2048
#define SDIM  5
#define WPB   4                 // warps per block
#define CHUNK 32                // delta steps staged per smem refill
#define NCHUNK (TT / CHUNK)

typedef unsigned long long ull;

// ---- packed f32x2 helpers (sm_100+/sm_103a) ----
__device__ __forceinline__ ull pack2(float lo, float hi) {
    ull r; asm("mov.b64 %0, {%1, %2};" : "=l"(r) : "f"(lo), "f"(hi)); return r;
}
__device__ __forceinline__ float sum2(ull a) {
    float lo, hi; asm("mov.b64 {%0, %1}, %2;" : "=f"(lo), "=f"(hi) : "l"(a));
    return lo + hi;
}
__device__ __forceinline__ ull mul2(ull a, ull b) {
    ull d; asm("mul.rn.f32x2 %0, %1, %2;" : "=l"(d) : "l"(a), "l"(b)); return d;
}
__device__ __forceinline__ ull add2(ull a, ull b) {
    ull d; asm("add.rn.f32x2 %0, %1, %2;" : "=l"(d) : "l"(a), "l"(b)); return d;
}
__device__ __forceinline__ void fma2(ull& d, ull a, ull b) {
    asm("fma.rn.f32x2 %0, %1, %2, %0;" : "+l"(d) : "l"(a), "l"(b));
}

// tanh(x) = 1 - 2/(exp2(2*log2(e)*x) + 1)  -- 5 instrs, 2 MUFU, ~1e-6 abs err.
__device__ __forceinline__ float tanh_fast(float x) {
    float e, r;
    asm("ex2.approx.f32 %0, %1;" : "=f"(e) : "f"(x * 2.885390081777926815f));
    asm("rcp.approx.f32 %0, %1;" : "=f"(r) : "f"(e + 1.0f));
    return fmaf(-2.0f, r, 1.0f);
}

__global__ __launch_bounds__(WPB * 32, 4)
void msc_seq_kernel(const float* __restrict__ delta,
                    const float* __restrict__ state0,
                    const float* __restrict__ W1, const float* __restrict__ b1,
                    const float* __restrict__ W2, const float* __restrict__ b2,
                    const float* __restrict__ W3, const float* __restrict__ b3,
                    float* __restrict__ out)
{
    __shared__ __align__(16) float sh1[WPB][32];         // h1 broadcast line
    __shared__ __align__(16) float sh2[WPB][32];         // h2 broadcast line
    __shared__ float shd[WPB][CHUNK * 3];                // staged delta

    const int lane = threadIdx.x & 31;
    const int warp = threadIdx.x >> 5;
    const int b    = blockIdx.x * WPB + warp;            // batch element
    const int lk   = (lane < SDIM) ? lane : 0;           // clamped output channel

    // ---- per-lane packed weights -------------------------------------------
    // w2p[p] = (W2[2p][j], W2[2p+1][j])          j = lane
    // mp[p]  = (M[2p][j],  M[2p+1][j]),  M = W3 @ W1_state   (carry update)
    // w3p[p] = (W3[2p][k], W3[2p+1][k])          k = lk      (output channel)
    ull w2p[16], mp[16], w3p[16];
#pragma unroll
    for (int p = 0; p < 16; p++) {
        const int i0 = 2 * p, i1 = 2 * p + 1;
        w2p[p] = pack2(W2[i0 * 32 + lane], W2[i1 * 32 + lane]);
        float m0 = 0.f, m1 = 0.f;
#pragma unroll
        for (int k = 0; k < SDIM; k++) {
            const float w1k = W1[k * 32 + lane];
            m0 = fmaf(W3[i0 * SDIM + k], w1k, m0);
            m1 = fmaf(W3[i1 * SDIM + k], w1k, m1);
        }
        mp[p]  = pack2(m0, m1);
        w3p[p] = pack2(W3[i0 * SDIM + lk], W3[i1 * SDIM + lk]);
    }
    const float w1d0 = W1[5 * 32 + lane];
    const float w1d1 = W1[6 * 32 + lane];
    const float w1d2 = W1[7 * 32 + lane];
    const float b2j  = b2[lane];
    const float b3k  = b3[lk];

    float gg = 0.f;                                      // g_j = (W1_s^T b3)_j
#pragma unroll
    for (int k = 0; k < SDIM; k++) gg = fmaf(b3[k], W1[k * 32 + lane], gg);

    // carry cb_j = b1_j + (W1_s^T s)_j ;  stk = s[lk] (valid for lanes 0..4)
    float cb = b1[lane];
#pragma unroll
    for (int k = 0; k < SDIM; k++) cb = fmaf(state0[b * SDIM + k], W1[k * 32 + lane], cb);
    float stk = state0[b * SDIM + lk];

    const float* dptr = delta + (size_t)b * (TT * 3);
    float*       optr = out   + (size_t)b * (TT * SDIM);
    const bool wr = (lane < SDIM);

    // prefetch first delta chunk
    float r0 = dptr[lane * 3 + 0];
    float r1 = dptr[lane * 3 + 1];
    float r2 = dptr[lane * 3 + 2];

    const ulonglong2* hp1 = (const ulonglong2*)sh1[warp];
    const ulonglong2* hp2 = (const ulonglong2*)sh2[warp];

    for (int c = 0; c < NCHUNK; c++) {
        __syncwarp();
        shd[warp][lane * 3 + 0] = r0;
        shd[warp][lane * 3 + 1] = r1;
        shd[warp][lane * 3 + 2] = r2;
        __syncwarp();
        if (c + 1 < NCHUNK) {
            const float* np = dptr + (size_t)(c + 1) * (CHUNK * 3);
            r0 = np[lane * 3 + 0];
            r1 = np[lane * 3 + 1];
            r2 = np[lane * 3 + 2];
        }

#pragma unroll 2
        for (int tl = 0; tl < CHUNK; tl++) {
            const float d0 = shd[warp][tl * 3 + 0];
            const float d1 = shd[warp][tl * 3 + 1];
            const float d2 = shd[warp][tl * 3 + 2];

            // ---- stage 1: h1_j = tanh(cb_j + d . W1_d[:,j]) ----
            float a = cb;
            a = fmaf(d0, w1d0, a);
            a = fmaf(d1, w1d1, a);
            a = fmaf(d2, w1d2, a);
            const float h1v = tanh_fast(a);

            sh1[warp][lane] = h1v;
            __syncwarp();

            // ---- stage 2: h2_j = tanh(h1 . W2[:,j] + b2_j)  (packed f32x2) ----
            ulonglong2 v0 = hp1[0], v1 = hp1[1], v2 = hp1[2], v3 = hp1[3];
            ulonglong2 v4 = hp1[4], v5 = hp1[5], v6 = hp1[6], v7 = hp1[7];
            ull a0 = mul2(v0.x, w2p[0]);
            ull a1 = mul2(v0.y, w2p[1]);
            fma2(a0, v1.x, w2p[2]);  fma2(a1, v1.y, w2p[3]);
            fma2(a0, v2.x, w2p[4]);  fma2(a1, v2.y, w2p[5]);
            fma2(a0, v3.x, w2p[6]);  fma2(a1, v3.y, w2p[7]);
            fma2(a0, v4.x, w2p[8]);  fma2(a1, v4.y, w2p[9]);
            fma2(a0, v5.x, w2p[10]); fma2(a1, v5.y, w2p[11]);
            fma2(a0, v6.x, w2p[12]); fma2(a1, v6.y, w2p[13]);
            fma2(a0, v7.x, w2p[14]); fma2(a1, v7.y, w2p[15]);
            const float h2v = tanh_fast(sum2(add2(a0, a1)) + b2j);

            sh2[warp][lane] = h2v;
            __syncwarp();

            // ---- stage 3: carry + output, both off the h2 broadcast ----
            ulonglong2 u0 = hp2[0], u1 = hp2[1], u2 = hp2[2], u3 = hp2[3];
            ulonglong2 u4 = hp2[4], u5 = hp2[5], u6 = hp2[6], u7 = hp2[7];
            ull c0 = mul2(u0.x, mp[0]);
            ull c1 = mul2(u0.y, mp[1]);
            ull s0 = mul2(u0.x, w3p[0]);
            ull s1 = mul2(u0.y, w3p[1]);
            fma2(c0, u1.x, mp[2]);  fma2(c1, u1.y, mp[3]);
            fma2(s0, u1.x, w3p[2]); fma2(s1, u1.y, w3p[3]);
            fma2(c0, u2.x, mp[4]);  fma2(c1, u2.y, mp[5]);
            fma2(s0, u2.x, w3p[4]); fma2(s1, u2.y, w3p[5]);
            fma2(c0, u3.x, mp[6]);  fma2(c1, u3.y, mp[7]);
            fma2(s0, u3.x, w3p[6]); fma2(s1, u3.y, w3p[7]);
            fma2(c0, u4.x, mp[8]);  fma2(c1, u4.y, mp[9]);
            fma2(s0, u4.x, w3p[8]); fma2(s1, u4.y, w3p[9]);
            fma2(c0, u5.x, mp[10]);  fma2(c1, u5.y, mp[11]);
            fma2(s0, u5.x, w3p[10]); fma2(s1, u5.y, w3p[11]);
            fma2(c0, u6.x, mp[12]);  fma2(c1, u6.y, mp[13]);
            fma2(s0, u6.x, w3p[12]); fma2(s1, u6.y, w3p[13]);
            fma2(c0, u7.x, mp[14]);  fma2(c1, u7.y, mp[15]);
            fma2(s0, u7.x, w3p[14]); fma2(s1, u7.y, w3p[15]);

            cb  += gg  + sum2(add2(c0, c1));   // carry update (replaces state recurrence)
            stk += b3k + sum2(add2(s0, s1));   // lane k's output channel

            if (wr) optr[lk] = stk;
            optr += SDIM;
        }
    }
}

extern "C" void kernel_launch(void* const* d_in, const int* in_sizes, int n_in,
                              void* d_out, int out_size)
{
    const float* delta  = (const float*)d_in[0];
    const float* state0 = (const float*)d_in[1];
    const float* W1     = (const float*)d_in[2];
    const float* b1     = (const float*)d_in[3];
    const float* W2     = (const float*)d_in[4];
    const float* b2     = (const float*)d_in[5];
    const float* W3     = (const float*)d_in[6];
    const float* b3     = (const float*)d_in[7];
    float* out = (float*)d_out;

    dim3 grid(BB / WPB);
    dim3 block(WPB * 32);
    msc_seq_kernel<<<grid, block>>>(delta, state0, W1, b1, W2, b2, W3, b3, out);
}

// round 4
// speedup vs baseline: 1.6307x; 1.6307x over previous
#include <cuda_runtime.h>

#define BB    4096
#define TT    2048
#define SDIM  5
#define WPB   4                 // warps per block
#define CHUNK 32                // delta steps staged per smem refill
#define NCHUNK (TT / CHUNK)

typedef unsigned long long ull;

// ---- packed f32x2 helpers (sm_100+/sm_103a) ----
__device__ __forceinline__ ull pack2(float lo, float hi) {
    ull r; asm("mov.b64 %0, {%1, %2};" : "=l"(r) : "f"(lo), "f"(hi)); return r;
}
__device__ __forceinline__ void unpack2(ull a, float& lo, float& hi) {
    asm("mov.b64 {%0, %1}, %2;" : "=f"(lo), "=f"(hi) : "l"(a));
}
__device__ __forceinline__ ull mul2(ull a, ull b) {
    ull d; asm("mul.rn.f32x2 %0, %1, %2;" : "=l"(d) : "l"(a), "l"(b)); return d;
}
__device__ __forceinline__ ull add2(ull a, ull b) {
    ull d; asm("add.rn.f32x2 %0, %1, %2;" : "=l"(d) : "l"(a), "l"(b)); return d;
}
__device__ __forceinline__ void fma2(ull& d, ull a, ull b) {
    asm("fma.rn.f32x2 %0, %1, %2, %0;" : "+l"(d) : "l"(a), "l"(b));
}

#define SC 2.885390081777926815f   // 2*log2(e): folded into W1/b1/W2/b2 at load

// tanh from a PRE-SCALED argument y = 2*log2(e)*x:
// tanh(x) = 1 - 2/(exp2(y)+1).  3 instrs + 1 FADD, 2 MUFU.
__device__ __forceinline__ float tanh_pre(float y) {
    float e, r;
    asm("ex2.approx.f32 %0, %1;" : "=f"(e) : "f"(y));
    asm("rcp.approx.f32 %0, %1;" : "=f"(r) : "f"(e + 1.0f));
    return fmaf(-2.0f, r, 1.0f);
}

__global__ __launch_bounds__(WPB * 32, 7)   // cap regs -> 28 warps/SM, one full wave
void msc_seq_kernel(const float* __restrict__ delta,
                    const float* __restrict__ state0,
                    const float* __restrict__ W1, const float* __restrict__ b1,
                    const float* __restrict__ W2, const float* __restrict__ b2,
                    const float* __restrict__ W3, const float* __restrict__ b3,
                    float* __restrict__ out)
{
    __shared__ __align__(16) float sh1[WPB][2][32];      // h1 broadcast, double-buffered
    __shared__ float shd[WPB][CHUNK * 3];                // staged delta

    const int lane = threadIdx.x & 31;
    const int warp = threadIdx.x >> 5;
    const int b    = blockIdx.x * WPB + warp;            // batch element owned by warp

    // ---- weights in registers (lane j = hidden channel j), tanh-prescaled ----
    float w1r[8];
#pragma unroll
    for (int i = 0; i < 8; i++)  w1r[i] = W1[i * 32 + lane] * SC;   // W1 col j (scaled)
    ull w2p[16];                                                    // W2 col j, packed+scaled
#pragma unroll
    for (int p = 0; p < 16; p++)
        w2p[p] = pack2(W2[(2 * p) * 32 + lane] * SC,
                       W2[(2 * p + 1) * 32 + lane] * SC);
    float w3r[5];
#pragma unroll
    for (int k = 0; k < 5; k++)  w3r[k] = W3[lane * SDIM + k];      // W3 row j (UNscaled)
    const float b1j = b1[lane] * SC;
    const float b2j = b2[lane] * SC;

    // ---- slot mapping for the merge-tree reduction ----
    // final D in lane j = full 32-lane sum of channel v(j):
    //   v = bit2 ? 4 : (bit3 ? (bit4 ? 3 : 2) : (bit4 ? 1 : 0))
    const int bit4 = (lane >> 4) & 1, bit3 = (lane >> 3) & 1, bit2 = (lane >> 2) & 1;
    const int vidx = bit2 ? 4 : (bit3 ? (bit4 ? 3 : 2) : (bit4 ? 1 : 0));
    const bool wr  = (lane == 0) | (lane == 4) | (lane == 8) | (lane == 16) | (lane == 24);

    const float b3v = b3[vidx];
    float stv = state0[b * SDIM + vidx];     // every lane carries its slot's state channel

    const float* dptr = delta + (size_t)b * (TT * 3);
    float*       optr = out   + (size_t)b * (TT * SDIM) + vidx;   // channel folded in

    // prefetch first delta chunk: lane L holds the 3 floats of its step slot
    float r0 = dptr[lane * 3 + 0];
    float r1 = dptr[lane * 3 + 1];
    float r2 = dptr[lane * 3 + 2];

    for (int c = 0; c < NCHUNK; c++) {
        __syncwarp();                        // prior chunk's delta reads done
        shd[warp][lane * 3 + 0] = r0;
        shd[warp][lane * 3 + 1] = r1;
        shd[warp][lane * 3 + 2] = r2;
        __syncwarp();
        if (c + 1 < NCHUNK) {
            const float* np = dptr + (size_t)(c + 1) * (CHUNK * 3);
            r0 = np[lane * 3 + 0];
            r1 = np[lane * 3 + 1];
            r2 = np[lane * 3 + 2];
        }

#pragma unroll 2
        for (int tl = 0; tl < CHUNK; tl++) {
            const int buf = tl & 1;
            const float d0 = shd[warp][tl * 3 + 0];
            const float d1 = shd[warp][tl * 3 + 1];
            const float d2 = shd[warp][tl * 3 + 2];

            // ---- broadcast state channels from slot lanes {0,16,8,24,4} ----
            const float s0b = __shfl_sync(0xffffffffu, stv, 0);
            const float s1b = __shfl_sync(0xffffffffu, stv, 16);
            const float s2b = __shfl_sync(0xffffffffu, stv, 8);
            const float s3b = __shfl_sync(0xffffffffu, stv, 24);
            const float s4b = __shfl_sync(0xffffffffu, stv, 4);

            // ---- stage 1: h1_j = tanh([s;d] . W1[:,j] + b1_j)  (prescaled) ----
            float a = b1j;
            a = fmaf(s0b, w1r[0], a);
            a = fmaf(s1b, w1r[1], a);
            a = fmaf(s2b, w1r[2], a);
            a = fmaf(s3b, w1r[3], a);
            a = fmaf(s4b, w1r[4], a);
            a = fmaf(d0,  w1r[5], a);
            a = fmaf(d1,  w1r[6], a);
            a = fmaf(d2,  w1r[7], a);
            const float h1v = tanh_pre(a);

            sh1[warp][buf][lane] = h1v;
            __syncwarp();

            // ---- stage 2: h2_j = tanh(h1 . W2[:,j] + b2_j)  (packed f32x2) ----
            const ulonglong2* hp = (const ulonglong2*)(&sh1[warp][buf][0]);
            ulonglong2 va = hp[0], vb = hp[1];
            ull a0 = mul2(va.x, w2p[0]);
            ull a1 = mul2(va.y, w2p[1]);
            va = hp[2];
            fma2(a0, vb.x, w2p[2]);  fma2(a1, vb.y, w2p[3]);
            vb = hp[3];
            fma2(a0, va.x, w2p[4]);  fma2(a1, va.y, w2p[5]);
            va = hp[4];
            fma2(a0, vb.x, w2p[6]);  fma2(a1, vb.y, w2p[7]);
            vb = hp[5];
            fma2(a0, va.x, w2p[8]);  fma2(a1, va.y, w2p[9]);
            va = hp[6];
            fma2(a0, vb.x, w2p[10]); fma2(a1, vb.y, w2p[11]);
            vb = hp[7];
            fma2(a0, va.x, w2p[12]); fma2(a1, va.y, w2p[13]);
            fma2(a0, vb.x, w2p[14]); fma2(a1, vb.y, w2p[15]);
            float lo, hi;
            unpack2(add2(a0, a1), lo, hi);
            const float h2v = tanh_pre(lo + hi + b2j);   // already prescaled

            // ---- stage 3: slot-merge reduction of p_k = h2_j * W3[j][k] ----
            const float p0 = h2v * w3r[0];
            const float p1 = h2v * w3r[1];
            const float p2 = h2v * w3r[2];
            const float p3 = h2v * w3r[3];
            float       p4 = h2v * w3r[4];

            // round 1 (xor 16): (p0,p1)->A, (p2,p3)->B, p4 butterfly
            float A  = bit4 ? p1 : p0;
            float Au = bit4 ? p0 : p1;
            A += __shfl_xor_sync(0xffffffffu, Au, 16);
            float B  = bit4 ? p3 : p2;
            float Bu = bit4 ? p2 : p3;
            B += __shfl_xor_sync(0xffffffffu, Bu, 16);
            p4 += __shfl_xor_sync(0xffffffffu, p4, 16);
            // round 2 (xor 8): (A,B)->C, p4 butterfly
            float Ct = bit3 ? B : A;
            float Cu = bit3 ? A : B;
            Ct += __shfl_xor_sync(0xffffffffu, Cu, 8);
            p4 += __shfl_xor_sync(0xffffffffu, p4, 8);
            // round 3 (xor 4): (C,p4)->D
            float D  = bit2 ? p4 : Ct;
            float Du = bit2 ? Ct : p4;
            D += __shfl_xor_sync(0xffffffffu, Du, 4);
            // rounds 4,5: plain butterfly
            D += __shfl_xor_sync(0xffffffffu, D, 2);
            D += __shfl_xor_sync(0xffffffffu, D, 1);

            stv += D + b3v;                  // every lane updates its slot channel

            if (wr) *optr = stv;             // lanes {0,16,8,24,4} -> channels {0..4}
            optr += SDIM;
        }
    }
}

extern "C" void kernel_launch(void* const* d_in, const int* in_sizes, int n_in,
                              void* d_out, int out_size)
{
    const float* delta  = (const float*)d_in[0];
    const float* state0 = (const float*)d_in[1];
    const float* W1     = (const float*)d_in[2];
    const float* b1     = (const float*)d_in[3];
    const float* W2     = (const float*)d_in[4];
    const float* b2     = (const float*)d_in[5];
    const float* W3     = (const float*)d_in[6];
    const float* b3     = (const float*)d_in[7];
    float* out = (float*)d_out;

    dim3 grid(BB / WPB);     // 4096 warps, one per batch element, one wave
    dim3 block(WPB * 32);
    msc_seq_kernel<<<grid, block>>>(delta, state0, W1, b1, W2, b2, W3, b3, out);
}

// round 5
// speedup vs baseline: 1.8761x; 1.1504x over previous
#include <cuda_runtime.h>

#define BB     4096
#define TT     2048
#define SDIM   5
#define WPB    4                 // warps per block
#define BPW    2                 // batch elements per warp (one per 16-lane half)
#define CHUNK  16                // delta steps staged per smem refill
#define NCHUNK (TT / CHUNK)

typedef unsigned long long ull;

// ---- packed f32x2 helpers (sm_100+/sm_103a) ----
__device__ __forceinline__ ull pack2(float lo, float hi) {
    ull r; asm("mov.b64 %0, {%1, %2};" : "=l"(r) : "f"(lo), "f"(hi)); return r;
}
__device__ __forceinline__ void unpack2(ull a, float& lo, float& hi) {
    asm("mov.b64 {%0, %1}, %2;" : "=f"(lo), "=f"(hi) : "l"(a));
}
__device__ __forceinline__ ull mul2(ull a, ull b) {
    ull d; asm("mul.rn.f32x2 %0, %1, %2;" : "=l"(d) : "l"(a), "l"(b)); return d;
}
__device__ __forceinline__ ull add2(ull a, ull b) {
    ull d; asm("add.rn.f32x2 %0, %1, %2;" : "=l"(d) : "l"(a), "l"(b)); return d;
}
__device__ __forceinline__ void fma2(ull& d, ull a, ull b) {
    asm("fma.rn.f32x2 %0, %1, %2, %0;" : "+l"(d) : "l"(a), "l"(b));
}

#define SC 2.885390081777926815f   // 2*log2(e): folded into W1/b1/W2/b2 at load

// tanh from a PRE-SCALED argument y = 2*log2(e)*x: tanh(x) = 1 - 2/(exp2(y)+1)
__device__ __forceinline__ float tanh_pre(float y) {
    float e, r;
    asm("ex2.approx.f32 %0, %1;" : "=f"(e) : "f"(y));
    asm("rcp.approx.f32 %0, %1;" : "=f"(r) : "f"(e + 1.0f));
    return fmaf(-2.0f, r, 1.0f);
}

// smem line sizes (floats), padded so batch-1 lines sit 16 banks off batch-0 lines
#define H1LINE 48                // 192B batch stride: 192 % 128 = 64 -> +16 banks
#define DLINE  (20 * 4)          // 320B batch stride: 320 % 128 = 64 -> +16 banks

__global__ __launch_bounds__(WPB * 32, 4)
void msc_seq_kernel(const float* __restrict__ delta,
                    const float* __restrict__ state0,
                    const float* __restrict__ W1, const float* __restrict__ b1,
                    const float* __restrict__ W2, const float* __restrict__ b2,
                    const float* __restrict__ W3, const float* __restrict__ b3,
                    float* __restrict__ out)
{
    __shared__ __align__(16) float sh1[WPB][BPW][H1LINE];   // h1 lines (one per batch)
    __shared__ __align__(16) float shd[WPB][BPW][DLINE];    // staged delta (float4/step)

    const int lane = threadIdx.x & 31;
    const int warp = threadIdx.x >> 5;
    const int h    = lane >> 4;          // which batch half
    const int hl   = lane & 15;          // lane within half
    const int b    = (blockIdx.x * WPB + warp) * BPW + h;   // this half's batch element

    const int j0 = hl, j1 = hl + 16;     // the two hidden channels this lane owns

    // ---- weights in registers (tanh-prescaled where they feed a tanh) ----
    float w1a[8], w1b[8];
#pragma unroll
    for (int i = 0; i < 8; i++) {
        w1a[i] = W1[i * 32 + j0] * SC;
        w1b[i] = W1[i * 32 + j1] * SC;
    }
    ull w2p[16], w2q[16];                // W2 columns j0 / j1, packed+scaled
#pragma unroll
    for (int p = 0; p < 16; p++) {
        w2p[p] = pack2(W2[(2 * p) * 32 + j0] * SC, W2[(2 * p + 1) * 32 + j0] * SC);
        w2q[p] = pack2(W2[(2 * p) * 32 + j1] * SC, W2[(2 * p + 1) * 32 + j1] * SC);
    }
    float w3a[5], w3b[5];
#pragma unroll
    for (int k = 0; k < 5; k++) {
        w3a[k] = W3[j0 * SDIM + k];      // UNscaled (feeds residual state)
        w3b[k] = W3[j1 * SDIM + k];
    }
    const float b1a = b1[j0] * SC, b1c = b1[j1] * SC;
    const float b2a = b2[j0] * SC, b2c = b2[j1] * SC;

    // ---- slot mapping (16-lane merge tree), half-local ----
    // final D in lane hl = 16-lane sum of channel v(hl):
    //   v = bit1 ? 4 : (bit2 ? (bit3 ? 3 : 2) : (bit3 ? 1 : 0))
    const int b3_ = (hl >> 3) & 1, b2_ = (hl >> 2) & 1, b1_ = (hl >> 1) & 1;
    const int vidx = b1_ ? 4 : (b2_ ? (b3_ ? 3 : 2) : (b3_ ? 1 : 0));
    const bool wr  = (hl == 0) | (hl == 8) | (hl == 4) | (hl == 12) | (hl == 2);

    const float b3v = b3[vidx];
    float stv = state0[b * SDIM + vidx];         // lane carries its slot's state channel

    const float* dptr = delta + (size_t)b * (TT * 3);
    float*       optr = out   + (size_t)b * (TT * SDIM) + vidx;

    // prefetch first delta chunk: lane (h,hl) holds step hl of batch b (3 floats)
    float r0 = dptr[hl * 3 + 0];
    float r1 = dptr[hl * 3 + 1];
    float r2 = dptr[hl * 3 + 2];

    const ulonglong2* hp = (const ulonglong2*)(&sh1[warp][h][0]);

    for (int c = 0; c < NCHUNK; c++) {
        __syncwarp();                            // prior chunk's delta reads done
        *(float4*)(&shd[warp][h][hl * 4]) = make_float4(r0, r1, r2, 0.f);
        __syncwarp();
        if (c + 1 < NCHUNK) {
            const float* np = dptr + (size_t)(c + 1) * (CHUNK * 3);
            r0 = np[hl * 3 + 0];
            r1 = np[hl * 3 + 1];
            r2 = np[hl * 3 + 2];
        }

#pragma unroll 4
        for (int tl = 0; tl < CHUNK; tl++) {
            const float4 dv = *(const float4*)(&shd[warp][h][tl * 4]);

            // ---- broadcast state channels within each half (width=16 shfl) ----
            const float s0b = __shfl_sync(0xffffffffu, stv, 0, 16);
            const float s1b = __shfl_sync(0xffffffffu, stv, 8, 16);
            const float s2b = __shfl_sync(0xffffffffu, stv, 4, 16);
            const float s3b = __shfl_sync(0xffffffffu, stv, 12, 16);
            const float s4b = __shfl_sync(0xffffffffu, stv, 2, 16);

            // ---- stage 1: two hidden channels per lane (prescaled) ----
            float aa = b1a, ac = b1c;
            aa = fmaf(s0b, w1a[0], aa);  ac = fmaf(s0b, w1b[0], ac);
            aa = fmaf(s1b, w1a[1], aa);  ac = fmaf(s1b, w1b[1], ac);
            aa = fmaf(s2b, w1a[2], aa);  ac = fmaf(s2b, w1b[2], ac);
            aa = fmaf(s3b, w1a[3], aa);  ac = fmaf(s3b, w1b[3], ac);
            aa = fmaf(s4b, w1a[4], aa);  ac = fmaf(s4b, w1b[4], ac);
            aa = fmaf(dv.x, w1a[5], aa); ac = fmaf(dv.x, w1b[5], ac);
            aa = fmaf(dv.y, w1a[6], aa); ac = fmaf(dv.y, w1b[6], ac);
            aa = fmaf(dv.z, w1a[7], aa); ac = fmaf(dv.z, w1b[7], ac);
            const float h1a = tanh_pre(aa);
            const float h1c = tanh_pre(ac);

            sh1[warp][h][j0] = h1a;              // banks 0-15 / 16-31 (pad-shifted)
            sh1[warp][h][j1] = h1c;
            __syncwarp();

            // ---- stage 2: h2 for both owned channels (packed f32x2) ----
            ulonglong2 va = hp[0], vb = hp[1];
            ull a0 = mul2(va.x, w2p[0]);
            ull a1 = mul2(va.y, w2p[1]);
            ull c0 = mul2(va.x, w2q[0]);
            ull c1 = mul2(va.y, w2q[1]);
            va = hp[2];
            fma2(a0, vb.x, w2p[2]);  fma2(a1, vb.y, w2p[3]);
            fma2(c0, vb.x, w2q[2]);  fma2(c1, vb.y, w2q[3]);
            vb = hp[3];
            fma2(a0, va.x, w2p[4]);  fma2(a1, va.y, w2p[5]);
            fma2(c0, va.x, w2q[4]);  fma2(c1, va.y, w2q[5]);
            va = hp[4];
            fma2(a0, vb.x, w2p[6]);  fma2(a1, vb.y, w2p[7]);
            fma2(c0, vb.x, w2q[6]);  fma2(c1, vb.y, w2q[7]);
            vb = hp[5];
            fma2(a0, va.x, w2p[8]);  fma2(a1, va.y, w2p[9]);
            fma2(c0, va.x, w2q[8]);  fma2(c1, va.y, w2q[9]);
            va = hp[6];
            fma2(a0, vb.x, w2p[10]); fma2(a1, vb.y, w2p[11]);
            fma2(c0, vb.x, w2q[10]); fma2(c1, vb.y, w2q[11]);
            vb = hp[7];
            fma2(a0, va.x, w2p[12]); fma2(a1, va.y, w2p[13]);
            fma2(c0, va.x, w2q[12]); fma2(c1, va.y, w2q[13]);
            fma2(a0, vb.x, w2p[14]); fma2(a1, vb.y, w2p[15]);
            fma2(c0, vb.x, w2q[14]); fma2(c1, vb.y, w2q[15]);
            float lo, hi;
            unpack2(add2(a0, a1), lo, hi);
            const float h2a = tanh_pre(lo + hi + b2a);
            unpack2(add2(c0, c1), lo, hi);
            const float h2c = tanh_pre(lo + hi + b2c);

            // ---- stage 3: per-lane channel products, then 16-lane slot merge ----
            const float p0 = fmaf(h2c, w3b[0], h2a * w3a[0]);
            const float p1 = fmaf(h2c, w3b[1], h2a * w3a[1]);
            const float p2 = fmaf(h2c, w3b[2], h2a * w3a[2]);
            const float p3 = fmaf(h2c, w3b[3], h2a * w3a[3]);
            float       p4 = fmaf(h2c, w3b[4], h2a * w3a[4]);

            // r1 (xor 8): (p0,p1)->A, (p2,p3)->B, p4 butterfly
            float A  = b3_ ? p1 : p0;
            float Au = b3_ ? p0 : p1;
            A += __shfl_xor_sync(0xffffffffu, Au, 8);
            float Bt = b3_ ? p3 : p2;
            float Bu = b3_ ? p2 : p3;
            Bt += __shfl_xor_sync(0xffffffffu, Bu, 8);
            p4 += __shfl_xor_sync(0xffffffffu, p4, 8);
            // r2 (xor 4): (A,B)->C, p4 butterfly
            float Ct = b2_ ? Bt : A;
            float Cu = b2_ ? A : Bt;
            Ct += __shfl_xor_sync(0xffffffffu, Cu, 4);
            p4 += __shfl_xor_sync(0xffffffffu, p4, 4);
            // r3 (xor 2): (C,p4)->D
            float D  = b1_ ? p4 : Ct;
            float Du = b1_ ? Ct : p4;
            D += __shfl_xor_sync(0xffffffffu, Du, 2);
            // r4 (xor 1): butterfly
            D += __shfl_xor_sync(0xffffffffu, D, 1);

            stv += D + b3v;                      // every lane updates its slot channel

            if (wr) *optr = stv;                 // 5 writer lanes per half
            optr += SDIM;
        }
    }
}

extern "C" void kernel_launch(void* const* d_in, const int* in_sizes, int n_in,
                              void* d_out, int out_size)
{
    const float* delta  = (const float*)d_in[0];
    const float* state0 = (const float*)d_in[1];
    const float* W1     = (const float*)d_in[2];
    const float* b1     = (const float*)d_in[3];
    const float* W2     = (const float*)d_in[4];
    const float* b2     = (const float*)d_in[5];
    const float* W3     = (const float*)d_in[6];
    const float* b3     = (const float*)d_in[7];
    float* out = (float*)d_out;

    dim3 grid(BB / (WPB * BPW));     // 512 blocks: 2048 warps, 2 batches each
    dim3 block(WPB * 32);
    msc_seq_kernel<<<grid, block>>>(delta, state0, W1, b1, W2, b2, W3, b3, out);
}